// round 2
// baseline (speedup 1.0000x reference)
#include <cuda_runtime.h>
#include <cuda_bf16.h>

#define N_NODES 50000
#define N_EDGES 800000
#define E2      850000   // edges + self loops
#define IN_F    128
#define HID     64
#define BN_EPS  1e-5f

// ---------------- scratch (device globals; no allocation allowed) ----------------
__device__ int    g_is64;
__device__ int    g_deg[N_NODES];
__device__ int    g_fill[N_NODES];
__device__ float  g_dinv[N_NODES];
__device__ int    g_rowptr[N_NODES + 1];
__device__ int    g_col[E2];
__device__ float  g_ew[E2];
__device__ float  g_hA[N_NODES * HID];
__device__ float  g_hB[N_NODES * HID];
__device__ float  g_h0[N_NODES * HID];
__device__ double g_sum[HID];
__device__ double g_sq[HID];
__device__ float  g_scale[HID];
__device__ float  g_shift[HID];

// ---------------- edge dtype detection ----------------
// If edge_index is int64 (little-endian, values < 50000), every odd int32 word
// is 0. For int32 data the odd words are src indices (all-zero prob ~ 0).
__global__ void detect_dtype_kernel(const int* __restrict__ e) {
    int nonzero = 0;
    for (int i = 0; i < 128; i++) nonzero += (e[2 * i + 1] != 0);
    g_is64 = (nonzero == 0) ? 1 : 0;
}

__device__ __forceinline__ int fetch_idx(const void* ei, long long pos) {
    int v;
    if (g_is64) v = (int)((const long long*)ei)[pos];
    else        v = ((const int*)ei)[pos];
    // clamp: crash insurance (wrong dtype shows as rel_err, not a fault)
    return min(max(v, 0), N_NODES - 1);
}

// ---------------- graph construction ----------------
__global__ void init_nodes_kernel() {
    int n = blockIdx.x * blockDim.x + threadIdx.x;
    if (n < N_NODES) { g_deg[n] = 1; g_fill[n] = 0; }  // deg starts at 1 (self loop)
}

__global__ void count_deg_kernel(const void* __restrict__ ei) {
    int e = blockIdx.x * blockDim.x + threadIdx.x;
    if (e < N_EDGES) {
        int d = fetch_idx(ei, (long long)N_EDGES + e);
        atomicAdd(&g_deg[d], 1);
    }
}

__global__ void dinv_kernel() {
    int n = blockIdx.x * blockDim.x + threadIdx.x;
    if (n < N_NODES) g_dinv[n] = rsqrtf((float)g_deg[n]);
}

// single-block exclusive prefix sum over 50000 degrees
__global__ void scan_kernel() {
    __shared__ int buf[1024];
    const int CH = (N_NODES + 1023) / 1024;  // 49
    int t = threadIdx.x;
    int beg = t * CH;
    int end = min(beg + CH, N_NODES);
    int local = 0;
    for (int i = beg; i < end; i++) local += g_deg[i];
    buf[t] = local;
    __syncthreads();
    for (int off = 1; off < 1024; off <<= 1) {
        int add = (t >= off) ? buf[t - off] : 0;
        __syncthreads();
        buf[t] += add;
        __syncthreads();
    }
    int run = buf[t] - local;  // exclusive prefix of this chunk
    for (int i = beg; i < end; i++) { g_rowptr[i] = run; run += g_deg[i]; }
    if (t == 1023) g_rowptr[N_NODES] = buf[1023];
}

__global__ void fill_csr_kernel(const void* __restrict__ ei) {
    int e = blockIdx.x * blockDim.x + threadIdx.x;
    if (e >= E2) return;
    int s, d;
    if (e < N_EDGES) {
        s = fetch_idx(ei, e);
        d = fetch_idx(ei, (long long)N_EDGES + e);
    } else {
        s = e - N_EDGES; d = s;
    }
    int pos = g_rowptr[d] + atomicAdd(&g_fill[d], 1);
    g_col[pos] = s;
    g_ew[pos]  = g_dinv[s] * g_dinv[d];
}

// ---------------- SpMM: warp per node, float2 per lane ----------------
// hout[n] = wacc * sum_e w[e]*hin[col[e]] (+ bias) (+ wh0 * h0[n])
__global__ __launch_bounds__(256) void spmm_kernel(
    const float* __restrict__ hin, float* __restrict__ hout,
    const float* __restrict__ bias, const float* __restrict__ h0p,
    float wacc, float wh0)
{
    int node = blockIdx.x * 8 + (threadIdx.x >> 5);
    int lane = threadIdx.x & 31;
    const float2* __restrict__ hin2 = (const float2*)hin;
    int beg = g_rowptr[node];
    int end = g_rowptr[node + 1];
    float2 a0 = make_float2(0.f, 0.f), a1 = a0, a2 = a0, a3 = a0;
    int e = beg;
    for (; e + 3 < end; e += 4) {
        int   s0 = g_col[e],   s1 = g_col[e+1], s2 = g_col[e+2], s3 = g_col[e+3];
        float w0 = g_ew[e],    w1 = g_ew[e+1],  w2 = g_ew[e+2],  w3 = g_ew[e+3];
        float2 v0 = hin2[s0*32 + lane];
        float2 v1 = hin2[s1*32 + lane];
        float2 v2 = hin2[s2*32 + lane];
        float2 v3 = hin2[s3*32 + lane];
        a0.x += w0*v0.x; a0.y += w0*v0.y;
        a1.x += w1*v1.x; a1.y += w1*v1.y;
        a2.x += w2*v2.x; a2.y += w2*v2.y;
        a3.x += w3*v3.x; a3.y += w3*v3.y;
    }
    for (; e < end; e++) {
        int s = g_col[e]; float w = g_ew[e];
        float2 v = hin2[s*32 + lane];
        a0.x += w*v.x; a0.y += w*v.y;
    }
    float2 acc;
    acc.x = (a0.x + a1.x) + (a2.x + a3.x);
    acc.y = (a0.y + a1.y) + (a2.y + a3.y);
    float2 r = make_float2(acc.x * wacc, acc.y * wacc);
    if (bias) {
        float2 b = ((const float2*)bias)[lane];
        r.x += b.x; r.y += b.y;
    }
    if (h0p) {
        float2 z = ((const float2*)h0p)[node*32 + lane];
        r.x += wh0 * z.x; r.y += wh0 * z.y;
    }
    ((float2*)hout)[node*32 + lane] = r;
}

// ---------------- BatchNorm ----------------
__global__ void bn_zero_kernel() {
    int f = threadIdx.x;
    if (f < HID) { g_sum[f] = 0.0; g_sq[f] = 0.0; }
}

__global__ __launch_bounds__(256) void bn_stats_kernel(const float* __restrict__ h) {
    int f   = threadIdx.x & 63;
    int grp = threadIdx.x >> 6;  // 0..3
    float s = 0.f, q = 0.f;
    for (int n = blockIdx.x * 4 + grp; n < N_NODES; n += gridDim.x * 4) {
        float v = h[n * HID + f];
        s += v; q += v * v;
    }
    __shared__ float ss[4][HID], qq[4][HID];
    ss[grp][f] = s; qq[grp][f] = q;
    __syncthreads();
    if (grp == 0) {
        s = (ss[0][f] + ss[1][f]) + (ss[2][f] + ss[3][f]);
        q = (qq[0][f] + qq[1][f]) + (qq[2][f] + qq[3][f]);
        atomicAdd(&g_sum[f], (double)s);
        atomicAdd(&g_sq[f],  (double)q);
    }
}

__global__ void bn_finalize_kernel(const float* __restrict__ g, const float* __restrict__ be) {
    int f = threadIdx.x;
    if (f >= HID) return;
    double mean = g_sum[f] / (double)N_NODES;
    double var  = g_sq[f] / (double)N_NODES - mean * mean;
    float sc = g[f] * rsqrtf((float)var + BN_EPS);
    g_scale[f] = sc;
    g_shift[f] = be[f] - (float)mean * sc;
}

__global__ __launch_bounds__(256) void bn_apply_kernel(float* __restrict__ h, float* __restrict__ cpy) {
    int i = blockIdx.x * blockDim.x + threadIdx.x;  // over N*HID/4 float4s
    if (i >= N_NODES * (HID / 4)) return;
    float4 v = ((const float4*)h)[i];
    int f = (i * 4) & (HID - 1);
    v.x = fmaxf(v.x * g_scale[f]     + g_shift[f],     0.f);
    v.y = fmaxf(v.y * g_scale[f + 1] + g_shift[f + 1], 0.f);
    v.z = fmaxf(v.z * g_scale[f + 2] + g_shift[f + 2], 0.f);
    v.w = fmaxf(v.w * g_scale[f + 3] + g_shift[f + 3], 0.f);
    ((float4*)h)[i] = v;
    if (cpy) ((float4*)cpy)[i] = v;
}

// ---------------- dense GEMM: C[N,64] = A[N,KIN] @ W[KIN,64] (+bias) ----------------
template <int KIN>
__global__ __launch_bounds__(256) void gemm_kernel(
    const float* __restrict__ A, const float* __restrict__ W,
    const float* __restrict__ bias, float* __restrict__ C)
{
    __shared__ float Ws[KIN * 64];
    __shared__ float As[32 * KIN];
    int tid = threadIdx.x;
    for (int i = tid; i < KIN * 64; i += 256) Ws[i] = W[i];
    int base = blockIdx.x * 32;
    for (int i = tid; i < 32 * KIN; i += 256) {
        int r = i / KIN, c = i - r * KIN;
        As[i] = (base + r < N_NODES) ? A[(base + r) * KIN + c] : 0.f;
    }
    __syncthreads();
    int f  = tid & 63;
    int ig = tid >> 6;  // 0..3, each handles 8 nodes
    float acc[8];
#pragma unroll
    for (int i = 0; i < 8; i++) acc[i] = 0.f;
#pragma unroll 8
    for (int k = 0; k < KIN; k++) {
        float wv = Ws[k * 64 + f];
#pragma unroll
        for (int i = 0; i < 8; i++)
            acc[i] += As[(ig * 8 + i) * KIN + k] * wv;
    }
    float bv = bias ? bias[f] : 0.f;
#pragma unroll
    for (int i = 0; i < 8; i++) {
        int n = base + ig * 8 + i;
        if (n < N_NODES) C[n * 64 + f] = acc[i] + bv;
    }
}

// ---------------- fused log-softmax over 64 classes ----------------
__global__ __launch_bounds__(256) void logsoftmax_kernel(
    const float* __restrict__ logits, float* __restrict__ out)
{
    int ng   = threadIdx.x >> 6;         // node group 0..3
    int node = blockIdx.x * 4 + ng;      // 50000 % 4 == 0, no guard
    int f    = threadIdx.x & 63;
    float v = logits[node * 64 + f];
    __shared__ float redm[4][2], reds[4][2];
    float m = v;
    for (int o = 16; o; o >>= 1) m = fmaxf(m, __shfl_xor_sync(0xffffffffu, m, o));
    int half = (threadIdx.x >> 5) & 1;
    if ((threadIdx.x & 31) == 0) redm[ng][half] = m;
    __syncthreads();
    m = fmaxf(redm[ng][0], redm[ng][1]);
    float e = __expf(v - m);
    float s = e;
    for (int o = 16; o; o >>= 1) s += __shfl_xor_sync(0xffffffffu, s, o);
    if ((threadIdx.x & 31) == 0) reds[ng][half] = s;
    __syncthreads();
    s = reds[ng][0] + reds[ng][1];
    out[node * 64 + f] = (v - m) - __logf(s);
}

// ---------------- host ----------------
static void run_bn(float* h, const float* g, const float* be, float* cpy) {
    bn_zero_kernel<<<1, 64>>>();
    bn_stats_kernel<<<256, 256>>>(h);
    bn_finalize_kernel<<<1, 64>>>(g, be);
    bn_apply_kernel<<<(N_NODES * (HID / 4) + 255) / 256, 256>>>(h, cpy);
}

extern "C" void kernel_launch(void* const* d_in, const int* in_sizes, int n_in,
                              void* d_out, int out_size) {
    const float* x   = (const float*)d_in[0];
    const void*  ei  = d_in[1];            // int32 or int64, detected on device
    const float* W1  = (const float*)d_in[2];
    const float* b1  = (const float*)d_in[3];
    const float* W2  = (const float*)d_in[4];
    const float* b2  = (const float*)d_in[5];
    const float* Wx  = (const float*)d_in[6];   // [2,64,64]
    const float* bx  = (const float*)d_in[7];   // [2,64]
    const float* g1  = (const float*)d_in[8];
    const float* be1 = (const float*)d_in[9];
    const float* g2  = (const float*)d_in[10];
    const float* be2 = (const float*)d_in[11];
    const float* g3  = (const float*)d_in[12];
    const float* be3 = (const float*)d_in[13];
    const float* Wfc = (const float*)d_in[14];
    const float* bfc = (const float*)d_in[15];
    float* out = (float*)d_out;

    float *hA, *hB, *h0;
    cudaGetSymbolAddress((void**)&hA, g_hA);
    cudaGetSymbolAddress((void**)&hB, g_hB);
    cudaGetSymbolAddress((void**)&h0, g_h0);

    // ---- build normalized CSR (by dst) ----
    detect_dtype_kernel<<<1, 1>>>((const int*)ei);
    init_nodes_kernel<<<(N_NODES + 255) / 256, 256>>>();
    count_deg_kernel<<<(N_EDGES + 255) / 256, 256>>>(ei);
    dinv_kernel<<<(N_NODES + 255) / 256, 256>>>();
    scan_kernel<<<1, 1024>>>();
    fill_csr_kernel<<<(E2 + 255) / 256, 256>>>(ei);

    const int GEMM_GRID = (N_NODES + 31) / 32;   // 1563
    const int SPMM_GRID = N_NODES / 8;           // 6250

    // ---- layer 1 (IN_F=128) ----
    gemm_kernel<128><<<GEMM_GRID, 256>>>(x, W1, nullptr, hB);
    spmm_kernel<<<SPMM_GRID, 256>>>(hB, hA, b1, nullptr, 1.f, 0.f);
    run_bn(hA, g1, be1, nullptr);
    // ---- layer 2 ----
    gemm_kernel<64><<<GEMM_GRID, 256>>>(hA, W2, nullptr, hB);
    spmm_kernel<<<SPMM_GRID, 256>>>(hB, hA, b2, nullptr, 1.f, 0.f);
    run_bn(hA, g2, be2, nullptr);
    // ---- extra layer 0 ----
    gemm_kernel<64><<<GEMM_GRID, 256>>>(hA, Wx, nullptr, hB);
    spmm_kernel<<<SPMM_GRID, 256>>>(hB, hA, bx, nullptr, 1.f, 0.f);
    run_bn(hA, g3, be3, nullptr);
    // ---- extra layer 1 (apply also writes h0) ----
    gemm_kernel<64><<<GEMM_GRID, 256>>>(hA, Wx + 64 * 64, nullptr, hB);
    spmm_kernel<<<SPMM_GRID, 256>>>(hB, hA, bx + 64, nullptr, 1.f, 0.f);
    run_bn(hA, g3, be3, h0);

    // ---- APPNP: 10 steps, ping-pong hA <-> hB ----
    float* cur = hA;
    float* nxt = hB;
    for (int it = 0; it < 10; it++) {
        spmm_kernel<<<SPMM_GRID, 256>>>(cur, nxt, nullptr, h0, 0.9f, 0.1f);
        float* t = cur; cur = nxt; nxt = t;
    }
    // after 10 steps result is in hA (cur == hA)

    // ---- head: FC + log_softmax ----
    gemm_kernel<64><<<GEMM_GRID, 256>>>(cur, Wfc, bfc, nxt);
    logsoftmax_kernel<<<N_NODES / 4, 256>>>(nxt, out);
}